// round 15
// baseline (speedup 1.0000x reference)
#include <cuda_runtime.h>
#include <cuda_bf16.h>
#include <cstdint>

typedef unsigned long long ull;

__device__ __forceinline__ uint32_t smem_u32(const void* p) {
    uint32_t a;
    asm("{ .reg .u64 tmp; cvta.to.shared.u64 tmp, %1; cvt.u32.u64 %0, tmp; }"
        : "=r"(a) : "l"(p));
    return a;
}
// pack two floats to bf16x2 (lo bits = a, hi bits = b)
__device__ __forceinline__ uint32_t pack_bf16x2(float a, float b) {
    uint32_t r;
    asm("cvt.rn.bf16x2.f32 %0, %1, %2;" : "=r"(r) : "f"(b), "f"(a));
    return r;
}
#define LDSM_X4(r, addr) \
    asm volatile("ldmatrix.sync.aligned.m8n8.x4.shared.b16 {%0,%1,%2,%3}, [%4];" \
                 : "=r"((r)[0]), "=r"((r)[1]), "=r"((r)[2]), "=r"((r)[3]) : "r"(addr))
#define MMA_BF16(c, a, b0v, b1v) \
    asm volatile("mma.sync.aligned.m16n8k16.row.col.f32.bf16.bf16.f32 " \
                 "{%0,%1,%2,%3}, {%4,%5,%6,%7}, {%8,%9}, {%0,%1,%2,%3};" \
                 : "+f"((c)[0]), "+f"((c)[1]), "+f"((c)[2]), "+f"((c)[3]) \
                 : "r"((a)[0]), "r"((a)[1]), "r"((a)[2]), "r"((a)[3]), \
                   "r"(b0v), "r"(b1v))

#define BSZ 128
#define FCK 25281
#define KPAD 25344      // 18 * 22 * 64
#define SK2 18
#define NCHUNK 22
#define FPITCH 72       // fc smem pitch bf16 (144 B = 9*16B, odd granules)
#define CPB 400         // conv0 smem pitch bytes (200 bf16 = 25*16B, odd granules)
#define C1P 56          // conv1 smem pitch bf16 (112 B = 7*16B, odd granules)

// scratch (no allocs allowed -> __device__ globals)
__device__ float g_y0[220 * 220 * BSZ];
__device__ float g_p0s[3025 * BSZ];
__device__ float g_p0ss[3025 * BSZ];
__device__ float g_lps[2][128][BSZ];        // ln stage-a partials
__device__ float g_lpss[2][128][BSZ];
__device__ float g_m0[BSZ], g_r0[BSZ];
__device__ float g_h1[110 * 110 * BSZ];
__device__ float g_y1[159 * 159 * BSZ];
__device__ float g_p1s[2809 * BSZ];
__device__ float g_p1ss[2809 * BSZ];
__device__ float g_m1[BSZ], g_r1[BSZ];
__device__ uint4 g_fT_hi[(size_t)BSZ * KPAD / 8];  // feat hi bf16, [b][k]
__device__ uint4 g_fT_lo[(size_t)BSZ * KPAD / 8];  // feat lo bf16, [b][k]
__device__ float g_part[SK2 * BSZ * 1000];

// ---------------------------------------------------------------------------
// conv0_mma [R14-proven]: per-location 128(b)x16(oc)x192(k) HMMA, bf16 hi/lo,
// weight loads issued first. grid (55,55), 256 threads; smem 115200 B.
// ---------------------------------------------------------------------------
__global__ void __launch_bounds__(256) conv0_mma_kernel(const float* __restrict__ x,
                                                        const float* __restrict__ w0,
                                                        const float* __restrict__ b0) {
    extern __shared__ __align__(16) char csb[];
    const uint32_t base = smem_u32(csb);
    const uint32_t PH = 0, PL = 128 * CPB, WH = 2 * 128 * CPB, WL = WH + 16 * CPB;
    const int i = blockIdx.x, j = blockIdx.y, t = threadIdx.x;

    const float2* wloc = (const float2*)(w0 + (size_t)(i * 55 + j) * 3072);
    float2 wreg[6];
#pragma unroll
    for (int p = 0; p < 6; p++) wreg[p] = __ldg(&wloc[p * 256 + t]);

    {
        const int b = t & 127, hp = t >> 7;
#pragma unroll 6
        for (int p = 0; p < 12; p++) {
            int p2 = hp * 12 + p;
            int c = p2 >> 3, di = p2 & 7;
            const float* src = x + (((size_t)(b * 3 + c) * 224) + (i * 4 + di)) * 224 + j * 4;
            float4 fa = *(const float4*)src;
            float4 fb = *(const float4*)(src + 4);
            uint32_t h0 = pack_bf16x2(fa.x, fa.y), h1 = pack_bf16x2(fa.z, fa.w);
            uint32_t h2 = pack_bf16x2(fb.x, fb.y), h3 = pack_bf16x2(fb.z, fb.w);
            uint32_t l0 = pack_bf16x2(fa.x - __uint_as_float(h0 << 16),
                                      fa.y - __uint_as_float(h0 & 0xFFFF0000u));
            uint32_t l1 = pack_bf16x2(fa.z - __uint_as_float(h1 << 16),
                                      fa.w - __uint_as_float(h1 & 0xFFFF0000u));
            uint32_t l2 = pack_bf16x2(fb.x - __uint_as_float(h2 << 16),
                                      fb.y - __uint_as_float(h2 & 0xFFFF0000u));
            uint32_t l3 = pack_bf16x2(fb.z - __uint_as_float(h3 << 16),
                                      fb.w - __uint_as_float(h3 & 0xFFFF0000u));
            uint32_t off = (uint32_t)b * CPB + (uint32_t)(c * 64 + di * 8) * 2;
            *(uint4*)(csb + PH + off) = make_uint4(h0, h1, h2, h3);
            *(uint4*)(csb + PL + off) = make_uint4(l0, l1, l2, l3);
        }
    }
#pragma unroll
    for (int p = 0; p < 6; p++) {
        int e2 = p * 256 + t;
        int oc = e2 / 96, kk = (e2 % 96) * 2;
        float2 wv = wreg[p];
        uint32_t ph = pack_bf16x2(wv.x, wv.y);
        uint32_t pl = pack_bf16x2(wv.x - __uint_as_float(ph << 16),
                                  wv.y - __uint_as_float(ph & 0xFFFF0000u));
        uint32_t off = (uint32_t)oc * CPB + (uint32_t)kk * 2;
        *(uint32_t*)(csb + WH + off) = ph;
        *(uint32_t*)(csb + WL + off) = pl;
    }
    __syncthreads();

    const int wid = t >> 5, lane = t & 31;
    const int g = lane >> 2, tg = lane & 3;
    const int tq = lane >> 3, tr = lane & 7;
    const int mbase = wid * 16;

    float acc[2][4];
#pragma unroll
    for (int nt = 0; nt < 2; nt++)
#pragma unroll
        for (int q = 0; q < 4; q++) acc[nt][q] = 0.f;

    const uint32_t raBase = (uint32_t)(mbase + (tq & 1) * 8 + tr) * CPB + (tq >> 1) * 16;
    const uint32_t rbBase = (uint32_t)((tq & 2) * 4 + tr) * CPB + (tq & 1) * 16;

#pragma unroll
    for (int kk = 0; kk < 12; kk++) {
        const uint32_t kb = kk * 32;
        uint32_t bh[4], bl[4], ah[4], al[4];
        LDSM_X4(bh, base + WH + rbBase + kb);
        LDSM_X4(bl, base + WL + rbBase + kb);
        LDSM_X4(ah, base + PH + raBase + kb);
        LDSM_X4(al, base + PL + raBase + kb);
        MMA_BF16(acc[0], ah, bh[0], bh[1]); MMA_BF16(acc[1], ah, bh[2], bh[3]);
        MMA_BF16(acc[0], ah, bl[0], bl[1]); MMA_BF16(acc[1], ah, bl[2], bl[3]);
        MMA_BF16(acc[0], al, bh[0], bh[1]); MMA_BF16(acc[1], al, bh[2], bh[3]);
    }

    int ocs[4] = {2 * tg, 2 * tg + 1, 8 + 2 * tg, 9 + 2 * tg};
    float bias[4];
#pragma unroll
    for (int q = 0; q < 4; q++) bias[q] = b0[(ocs[q] * 55 + i) * 55 + j];
    const int blk = j * 55 + i;

#pragma unroll
    for (int rh = 0; rh < 2; rh++) {
        int b = mbase + rh * 8 + g;
        float vals[4] = {acc[0][2 * rh], acc[0][2 * rh + 1],
                         acc[1][2 * rh], acc[1][2 * rh + 1]};
        float s = 0.f, ss = 0.f;
#pragma unroll
        for (int q = 0; q < 4; q++) {
            float v = fmaxf(vals[q] + bias[q], 0.f);
            int oc = ocs[q];
            g_y0[((i * 4 + (oc >> 2)) * 220 + (j * 4 + (oc & 3))) * 128 + b] = v;
            s += v;
            ss = fmaf(v, v, ss);
        }
        s  += __shfl_xor_sync(0xffffffffu, s, 1);
        s  += __shfl_xor_sync(0xffffffffu, s, 2);
        ss += __shfl_xor_sync(0xffffffffu, ss, 1);
        ss += __shfl_xor_sync(0xffffffffu, ss, 2);
        if (tg == 0) {
            g_p0s[blk * 128 + b]  = s;
            g_p0ss[blk * 128 + b] = ss;
        }
    }
}

// ---------------------------------------------------------------------------
// ln stage a: COALESCED row sweeps. grid 128, 256 threads.
// Block g reduces rows [g*chunk, ...); thread lanes vary b (coalesced);
// two k-interleaved halves combined through smem.
// ---------------------------------------------------------------------------
__global__ void __launch_bounds__(256) ln2a_kernel(int which) {
    const float* ps  = which ? g_p1s  : g_p0s;
    const float* pss = which ? g_p1ss : g_p0ss;
    const int nblk   = which ? 2809 : 3025;
    const int chunk  = (nblk + 127) >> 7;
    const int gb = blockIdx.x, t = threadIdx.x;
    const int b = t & 127, sub = t >> 7;
    const int k0 = gb * chunk;
    const int k1 = min(k0 + chunk, nblk);
    float s = 0.f, ss = 0.f;
    for (int k = k0 + sub; k < k1; k += 2) {
        s  += ps[k * 128 + b];
        ss += pss[k * 128 + b];
    }
    __shared__ float s1[256], s2[256];
    s1[t] = s; s2[t] = ss;
    __syncthreads();
    if (t < 128) {
        g_lps[which][gb][t]  = s1[t] + s1[t + 128];
        g_lpss[which][gb][t] = s2[t] + s2[t + 128];
    }
}

// ---------------------------------------------------------------------------
// ln stage b: final reduce over 128 partial rows (coalesced). grid 1, 128 thr.
// ---------------------------------------------------------------------------
__global__ void __launch_bounds__(128) ln2b_kernel(int which) {
    float* gm = which ? g_m1 : g_m0;
    float* gr = which ? g_r1 : g_r0;
    const float invn = which ? (1.f / 25281.f) : (1.f / 48400.f);
    const int t = threadIdx.x;
    float s = 0.f, ss = 0.f;
#pragma unroll 8
    for (int g2 = 0; g2 < 128; g2++) {
        s  += g_lps[which][g2][t];
        ss += g_lpss[which][g2][t];
    }
    float m = s * invn;
    gm[t] = m;
    gr[t] = rsqrtf(ss * invn - m * m + 1e-5f);
}

// ---------------------------------------------------------------------------
// normalize (layer0) + 2x2 maxpool -> g_h1 [pos][b], float4 over b (MLP 16)
// ---------------------------------------------------------------------------
__global__ void norm_pool_kernel(const float* __restrict__ g0,
                                 const float* __restrict__ be0) {
    int idx = blockIdx.x * 256 + threadIdx.x;
    if (idx >= 32 * 110 * 110) return;
    int bq = idx & 31, pos = idx >> 5;
    int r = pos / 110, c = pos - r * 110;
    float4 m  = *(const float4*)&g_m0[bq * 4];
    float4 rs = *(const float4*)&g_r0[bq * 4];
    float4 mx = make_float4(-3.4e38f, -3.4e38f, -3.4e38f, -3.4e38f);
#pragma unroll
    for (int dr = 0; dr < 2; dr++)
#pragma unroll
        for (int dc = 0; dc < 2; dc++) {
            int P = (2 * r + dr) * 220 + 2 * c + dc;
            float4 y = *(const float4*)&g_y0[P * 128 + bq * 4];
            float gv = g0[P], bv = be0[P];
            mx.x = fmaxf(mx.x, fmaf((y.x - m.x) * rs.x, gv, bv));
            mx.y = fmaxf(mx.y, fmaf((y.y - m.y) * rs.y, gv, bv));
            mx.z = fmaxf(mx.z, fmaf((y.z - m.z) * rs.z, gv, bv));
            mx.w = fmaxf(mx.w, fmaf((y.w - m.w) * rs.w, gv, bv));
        }
    *(float4*)&g_h1[pos * 128 + bq * 4] = mx;
}

// ---------------------------------------------------------------------------
// conv1_mma [R11-proven]: per-location 128(b) x 16(oc; 9 real) x 48(k; 36
// real) HMMA, bf16 hi/lo split. grid (53,53), 128 threads (4 warps).
// ---------------------------------------------------------------------------
__global__ void __launch_bounds__(128) conv1_mma_kernel(const float* __restrict__ w1,
                                                        const float* __restrict__ b1) {
    __shared__ __align__(16) __nv_bfloat16 c1[2 * 128 * C1P + 2 * 16 * C1P];
    const uint32_t base = smem_u32(c1);
    const uint32_t PHE = 0, PLE = 128 * C1P, WHE = 2 * 128 * C1P, WLE = WHE + 16 * C1P;
    const int i = blockIdx.x, j = blockIdx.y, t = threadIdx.x;

    {
        uint32_t* wz = (uint32_t*)(c1 + WHE);
        for (int p = t; p < 896; p += 128) wz[p] = 0;
    }
    {
        uint32_t* p32 = (uint32_t*)c1;
#pragma unroll
        for (int w = 18; w < 24; w++) {
            p32[t * 28 + w] = 0;
            p32[128 * 28 + t * 28 + w] = 0;
        }
    }
    {
        uint32_t* ph32 = (uint32_t*)c1;
        uint32_t* pl32 = ph32 + 128 * 28;
#pragma unroll 6
        for (int k2 = 0; k2 < 18; k2++) {
            int k0 = 2 * k2;
            int di0 = k0 / 6, dj0 = k0 - di0 * 6;
            int di1 = (k0 + 1) / 6, dj1 = (k0 + 1) - di1 * 6;
            float v0 = g_h1[((2 * i + di0) * 110 + 2 * j + dj0) * 128 + t];
            float v1 = g_h1[((2 * i + di1) * 110 + 2 * j + dj1) * 128 + t];
            uint32_t ph = pack_bf16x2(v0, v1);
            uint32_t pl = pack_bf16x2(v0 - __uint_as_float(ph << 16),
                                      v1 - __uint_as_float(ph & 0xFFFF0000u));
            ph32[t * 28 + k2] = ph;
            pl32[t * 28 + k2] = pl;
        }
    }
    {
        const float* wloc = w1 + (i * 53 + j) * 324;
        for (int e = t; e < 324; e += 128) {
            int oc = e / 36, kk = e - oc * 36;
            float v = wloc[e];
            __nv_bfloat16 h = __float2bfloat16(v);
            __nv_bfloat16 l = __float2bfloat16(v - __bfloat162float(h));
            c1[WHE + oc * C1P + kk] = h;
            c1[WLE + oc * C1P + kk] = l;
        }
    }
    __syncthreads();

    const int wid = t >> 5, lane = t & 31;
    const int g = lane >> 2, tg = lane & 3;
    const int tq = lane >> 3, tr = lane & 7;
    const int mbase = wid * 32;

    float acc[2][2][4];
#pragma unroll
    for (int mt = 0; mt < 2; mt++)
#pragma unroll
        for (int nt = 0; nt < 2; nt++)
#pragma unroll
            for (int q = 0; q < 4; q++) acc[mt][nt][q] = 0.f;

    const uint32_t aOff = (uint32_t)((tq & 1) * 8 + tr) * 112 + (tq >> 1) * 16;
    const uint32_t bOff = (uint32_t)((tq & 2) * 4 + tr) * 112 + (tq & 1) * 16;

#pragma unroll
    for (int k16 = 0; k16 < 3; k16++) {
        const uint32_t kb = k16 * 32;
        uint32_t bh[4], bl[4];
        LDSM_X4(bh, base + WHE * 2 + bOff + kb);
        LDSM_X4(bl, base + WLE * 2 + bOff + kb);
#pragma unroll
        for (int mt = 0; mt < 2; mt++) {
            uint32_t ah[4], al[4];
            uint32_t ra = (uint32_t)(mbase + mt * 16) * 112 + aOff + kb;
            LDSM_X4(ah, base + ra);
            LDSM_X4(al, base + PLE * 2 + ra);
            MMA_BF16(acc[mt][0], ah, bh[0], bh[1]); MMA_BF16(acc[mt][1], ah, bh[2], bh[3]);
            MMA_BF16(acc[mt][0], ah, bl[0], bl[1]); MMA_BF16(acc[mt][1], ah, bl[2], bl[3]);
            MMA_BF16(acc[mt][0], al, bh[0], bh[1]); MMA_BF16(acc[mt][1], al, bh[2], bh[3]);
        }
    }

    const int loc = i * 53 + j;
    const int oc0 = 2 * tg, oc1 = 2 * tg + 1;
    const float bv0 = b1[(oc0 * 53 + i) * 53 + j];
    const float bv1 = b1[(oc1 * 53 + i) * 53 + j];
    const float bv8 = (tg == 0) ? b1[(8 * 53 + i) * 53 + j] : 0.f;

#pragma unroll
    for (int mt = 0; mt < 2; mt++)
#pragma unroll
        for (int rh = 0; rh < 2; rh++) {
            int b = mbase + mt * 16 + rh * 8 + g;
            float s = 0.f, ss = 0.f;
            float v0 = fmaxf(acc[mt][0][2 * rh] + bv0, 0.f);
            float v1 = fmaxf(acc[mt][0][2 * rh + 1] + bv1, 0.f);
            g_y1[((i * 3 + oc0 / 3) * 159 + (j * 3 + oc0 % 3)) * 128 + b] = v0;
            g_y1[((i * 3 + oc1 / 3) * 159 + (j * 3 + oc1 % 3)) * 128 + b] = v1;
            s = v0 + v1;
            ss = fmaf(v0, v0, 0.f);
            ss = fmaf(v1, v1, ss);
            if (tg == 0) {
                float v8 = fmaxf(acc[mt][1][2 * rh] + bv8, 0.f);
                g_y1[((i * 3 + 2) * 159 + (j * 3 + 2)) * 128 + b] = v8;
                s += v8;
                ss = fmaf(v8, v8, ss);
            }
            s  += __shfl_xor_sync(0xffffffffu, s, 1);
            s  += __shfl_xor_sync(0xffffffffu, s, 2);
            ss += __shfl_xor_sync(0xffffffffu, ss, 1);
            ss += __shfl_xor_sync(0xffffffffu, ss, 2);
            if (tg == 0) {
                g_p1s[loc * 128 + b]  = s;
                g_p1ss[loc * 128 + b] = ss;
            }
        }
}

// ---------------------------------------------------------------------------
// norm1t: normalize layer1 + transpose to [b][k] + bf16 hi/lo split.
// ---------------------------------------------------------------------------
__global__ void __launch_bounds__(256) norm1t_kernel(const float* __restrict__ g1,
                                                     const float* __restrict__ be1) {
    __shared__ float Tb[64][129];
    const int k0 = blockIdx.x * 64;
    const int t = threadIdx.x;
#pragma unroll
    for (int p = 0; p < 8; p++) {
        int e = p * 256 + t;
        int kl = e >> 5, bq = e & 31;
        int k = k0 + kl;
        float4 v = make_float4(0.f, 0.f, 0.f, 0.f);
        if (k < FCK) {
            float4 y = *(const float4*)&g_y1[k * 128 + bq * 4];
            float4 m = *(const float4*)&g_m1[bq * 4];
            float4 r = *(const float4*)&g_r1[bq * 4];
            float gk = g1[k], bk = be1[k];
            v.x = fmaf((y.x - m.x) * r.x, gk, bk);
            v.y = fmaf((y.y - m.y) * r.y, gk, bk);
            v.z = fmaf((y.z - m.z) * r.z, gk, bk);
            v.w = fmaf((y.w - m.w) * r.w, gk, bk);
        }
        Tb[kl][bq * 4 + 0] = v.x;
        Tb[kl][bq * 4 + 1] = v.y;
        Tb[kl][bq * 4 + 2] = v.z;
        Tb[kl][bq * 4 + 3] = v.w;
    }
    __syncthreads();

    const int b = t >> 1, half = t & 1;
    uint32_t oh[16], ol[16];
#pragma unroll
    for (int u = 0; u < 16; u++) {
        float v0 = Tb[half * 32 + 2 * u][b];
        float v1 = Tb[half * 32 + 2 * u + 1][b];
        uint32_t ph = pack_bf16x2(v0, v1);
        float h0 = __uint_as_float(ph << 16);
        float h1 = __uint_as_float(ph & 0xFFFF0000u);
        oh[u] = ph;
        ol[u] = pack_bf16x2(v0 - h0, v1 - h1);
    }
    uint32_t* dh = (uint32_t*)g_fT_hi + (size_t)b * (KPAD / 2) + (k0 + half * 32) / 2;
    uint32_t* dl = (uint32_t*)g_fT_lo + (size_t)b * (KPAD / 2) + (k0 + half * 32) / 2;
#pragma unroll
    for (int q = 0; q < 4; q++) {
        ((uint4*)dh)[q] = make_uint4(oh[4 * q], oh[4 * q + 1], oh[4 * q + 2], oh[4 * q + 3]);
        ((uint4*)dl)[q] = make_uint4(ol[4 * q], ol[4 * q + 1], ol[4 * q + 2], ol[4 * q + 3]);
    }
}

// ---------------------------------------------------------------------------
// fc_mma [R10-proven]: bf16 hi/lo-split HMMA GEMM, register-pipelined.
// grid (8, 18), 256 threads (8 warps).
// ---------------------------------------------------------------------------
__global__ void __launch_bounds__(256) fc_mma_kernel(const float* __restrict__ fcw) {
    extern __shared__ __align__(16) __nv_bfloat16 sb[];
    __nv_bfloat16* Wh = sb;                  // [128][72]
    __nv_bfloat16* Wl = Wh + 128 * FPITCH;
    __nv_bfloat16* Fh = Wl + 128 * FPITCH;
    __nv_bfloat16* Fl = Fh + 128 * FPITCH;
    const uint32_t base = smem_u32(sb);
    const uint32_t WH_OFF = 0, WL_OFF = 128 * FPITCH * 2,
                   FH_OFF = 2 * 128 * FPITCH * 2, FL_OFF = 3 * 128 * FPITCH * 2;

    const int t = threadIdx.x, wid = t >> 5, lane = t & 31;
    const int g = lane >> 2, tg = lane & 3;
    const int tq = lane >> 3, tr = lane & 7;
    const int nbase = blockIdx.x * 128;
    const int sk = blockIdx.y;

    float acc[16][4];
#pragma unroll
    for (int bt = 0; bt < 16; bt++)
#pragma unroll
        for (int q = 0; q < 4; q++) acc[bt][q] = 0.f;

    const uint32_t aRow = wid * 16 + (tq & 1) * 8 + tr;
    const uint32_t aKof = (tq >> 1) * 8;
    const uint32_t bRowB = (tq & 2) * 4 + tr;
    const uint32_t bKof = (tq & 1) * 8;

    float wv[32];
    uint4 fh[4], fl[4];
    const int wrow = t >> 6, wc0 = (t & 63);
    const int frow = t >> 3, fq = t & 7;

#define FC_LOAD_TILE(K0) do { \
    _Pragma("unroll") \
    for (int p = 0; p < 32; p++) { \
        int row = wrow + p * 4, k = (K0) + wc0; \
        int ng = nbase + row; \
        wv[p] = (ng < 1000 && k < FCK) ? __ldg(&fcw[ng * FCK + k]) : 0.f; \
    } \
    _Pragma("unroll") \
    for (int p = 0; p < 4; p++) { \
        int b = frow + p * 32; \
        size_t idx = ((size_t)b * KPAD + (K0)) / 8 + fq; \
        fh[p] = g_fT_hi[idx]; \
        fl[p] = g_fT_lo[idx]; \
    } \
} while (0)

    FC_LOAD_TILE(sk * NCHUNK * 64);

    for (int it = 0; it < NCHUNK; it++) {
        __syncthreads();
#pragma unroll
        for (int p = 0; p < 32; p++) {
            int row = wrow + p * 4, c = wc0;
            float v = wv[p];
            __nv_bfloat16 h = __float2bfloat16(v);
            __nv_bfloat16 l = __float2bfloat16(v - __bfloat162float(h));
            Wh[row * FPITCH + c] = h;
            Wl[row * FPITCH + c] = l;
        }
#pragma unroll
        for (int p = 0; p < 4; p++) {
            int b = frow + p * 32;
            *(uint4*)&Fh[b * FPITCH + fq * 8] = fh[p];
            *(uint4*)&Fl[b * FPITCH + fq * 8] = fl[p];
        }
        __syncthreads();
        if (it + 1 < NCHUNK) FC_LOAD_TILE((sk * NCHUNK + it + 1) * 64);

#pragma unroll
        for (int k16 = 0; k16 < 4; k16++) {
            uint32_t ak = (k16 * 16 + aKof) * 2;
            uint32_t ah[4], al[4];
            LDSM_X4(ah, base + WH_OFF + aRow * (FPITCH * 2) + ak);
            LDSM_X4(al, base + WL_OFF + aRow * (FPITCH * 2) + ak);
            uint32_t bk = (k16 * 16 + bKof) * 2;
#pragma unroll
            for (int bt2 = 0; bt2 < 8; bt2++) {
                uint32_t brow = bt2 * 16 + bRowB;
                uint32_t bh[4], bl[4];
                LDSM_X4(bh, base + FH_OFF + brow * (FPITCH * 2) + bk);
                LDSM_X4(bl, base + FL_OFF + brow * (FPITCH * 2) + bk);
                MMA_BF16(acc[2 * bt2],     ah, bh[0], bh[1]);
                MMA_BF16(acc[2 * bt2 + 1], ah, bh[2], bh[3]);
                MMA_BF16(acc[2 * bt2],     ah, bl[0], bl[1]);
                MMA_BF16(acc[2 * bt2 + 1], ah, bl[2], bl[3]);
                MMA_BF16(acc[2 * bt2],     al, bh[0], bh[1]);
                MMA_BF16(acc[2 * bt2 + 1], al, bh[2], bh[3]);
            }
        }
    }

    float* outp = g_part + sk * (BSZ * 1000);
    const int n0 = nbase + wid * 16 + g;
    const int n1 = n0 + 8;
#pragma unroll
    for (int bt = 0; bt < 16; bt++) {
        int b0 = bt * 8 + tg * 2;
        if (n0 < 1000) {
            outp[b0 * 1000 + n0]       = acc[bt][0];
            outp[(b0 + 1) * 1000 + n0] = acc[bt][1];
        }
        if (n1 < 1000) {
            outp[b0 * 1000 + n1]       = acc[bt][2];
            outp[(b0 + 1) * 1000 + n1] = acc[bt][3];
        }
    }
}

// ---------------------------------------------------------------------------
// reduce split-K partials (fixed order -> deterministic) + bias + softmax
// float4 over n (1000 = 4*250)
// ---------------------------------------------------------------------------
__global__ void softmax_kernel(const float* __restrict__ fcb,
                               float* __restrict__ out) {
    int b = blockIdx.x, t = threadIdx.x;
    __shared__ __align__(16) float lg[1000];
    __shared__ float red[8];
    __shared__ float bc;

    if (t < 250) {
        float4 v = *(const float4*)&fcb[4 * t];
#pragma unroll 6
        for (int s = 0; s < SK2; s++) {
            float4 pv = *(const float4*)&g_part[(s * BSZ + b) * 1000 + 4 * t];
            v.x += pv.x; v.y += pv.y; v.z += pv.z; v.w += pv.w;
        }
        *(float4*)&lg[4 * t] = v;
    }
    __syncthreads();

    float mx = -3.4e38f;
    for (int n = t; n < 1000; n += 256) mx = fmaxf(mx, lg[n]);
    for (int o = 16; o; o >>= 1) mx = fmaxf(mx, __shfl_xor_sync(0xffffffffu, mx, o));
    if ((t & 31) == 0) red[t >> 5] = mx;
    __syncthreads();
    if (t == 0) {
        float m = red[0];
        for (int w = 1; w < 8; w++) m = fmaxf(m, red[w]);
        bc = m;
    }
    __syncthreads();
    mx = bc;

    float s = 0.f;
    for (int n = t; n < 1000; n += 256) s += expf(lg[n] - mx);
    for (int o = 16; o; o >>= 1) s += __shfl_xor_sync(0xffffffffu, s, o);
    __syncthreads();
    if ((t & 31) == 0) red[t >> 5] = s;
    __syncthreads();
    if (t == 0) {
        float tot = 0.f;
        for (int w = 0; w < 8; w++) tot += red[w];
        bc = 1.f / tot;
    }
    __syncthreads();
    float inv = bc;
    for (int n = t; n < 1000; n += 256)
        out[b * 1000 + n] = expf(lg[n] - mx) * inv;
}

// ---------------------------------------------------------------------------

extern "C" void kernel_launch(void* const* d_in, const int* in_sizes, int n_in,
                              void* d_out, int out_size) {
    const float* x   = (const float*)d_in[0];
    const float* w0  = (const float*)d_in[1];
    const float* b0  = (const float*)d_in[2];
    const float* g0  = (const float*)d_in[3];
    const float* be0 = (const float*)d_in[4];
    const float* w1  = (const float*)d_in[5];
    const float* b1  = (const float*)d_in[6];
    const float* g1  = (const float*)d_in[7];
    const float* be1 = (const float*)d_in[8];
    const float* fcw = (const float*)d_in[9];
    const float* fcb = (const float*)d_in[10];
    float* out = (float*)d_out;

    const int smem0 = 2 * 128 * CPB + 2 * 16 * CPB;                   // 115200 B
    cudaFuncSetAttribute(conv0_mma_kernel, cudaFuncAttributeMaxDynamicSharedMemorySize, smem0);
    const int smemFC = 4 * 128 * FPITCH * 2;                          // 73728 B
    cudaFuncSetAttribute(fc_mma_kernel, cudaFuncAttributeMaxDynamicSharedMemorySize, smemFC);

    conv0_mma_kernel<<<dim3(55, 55), 256, smem0>>>(x, w0, b0);
    ln2a_kernel<<<128, 256>>>(0);
    ln2b_kernel<<<1, 128>>>(0);
    norm_pool_kernel<<<(32 * 110 * 110 + 255) / 256, 256>>>(g0, be0);
    conv1_mma_kernel<<<dim3(53, 53), 128>>>(w1, b1);
    ln2a_kernel<<<128, 256>>>(1);
    ln2b_kernel<<<1, 128>>>(1);
    norm1t_kernel<<<396, 256>>>(g1, be1);
    fc_mma_kernel<<<dim3(8, SK2), 256, smemFC>>>(fcw);
    softmax_kernel<<<128, 256>>>(fcb, out);
}

// round 16
// speedup vs baseline: 1.0379x; 1.0379x over previous
#include <cuda_runtime.h>
#include <cuda_bf16.h>
#include <cstdint>

typedef unsigned long long ull;

__device__ __forceinline__ uint32_t smem_u32(const void* p) {
    uint32_t a;
    asm("{ .reg .u64 tmp; cvta.to.shared.u64 tmp, %1; cvt.u32.u64 %0, tmp; }"
        : "=r"(a) : "l"(p));
    return a;
}
// pack two floats to bf16x2 (lo bits = a, hi bits = b)
__device__ __forceinline__ uint32_t pack_bf16x2(float a, float b) {
    uint32_t r;
    asm("cvt.rn.bf16x2.f32 %0, %1, %2;" : "=r"(r) : "f"(b), "f"(a));
    return r;
}
#define LDSM_X4(r, addr) \
    asm volatile("ldmatrix.sync.aligned.m8n8.x4.shared.b16 {%0,%1,%2,%3}, [%4];" \
                 : "=r"((r)[0]), "=r"((r)[1]), "=r"((r)[2]), "=r"((r)[3]) : "r"(addr))
#define MMA_BF16(c, a, b0v, b1v) \
    asm volatile("mma.sync.aligned.m16n8k16.row.col.f32.bf16.bf16.f32 " \
                 "{%0,%1,%2,%3}, {%4,%5,%6,%7}, {%8,%9}, {%0,%1,%2,%3};" \
                 : "+f"((c)[0]), "+f"((c)[1]), "+f"((c)[2]), "+f"((c)[3]) \
                 : "r"((a)[0]), "r"((a)[1]), "r"((a)[2]), "r"((a)[3]), \
                   "r"(b0v), "r"(b1v))

#define BSZ 128
#define FCK 25281
#define KPAD 25344      // 18 * 22 * 64
#define SK2 18
#define NCHUNK 22
#define FPITCH 72       // fc smem pitch bf16 (144 B = 9*16B, odd granules)
#define CPB 400         // conv0 smem pitch bytes (200 bf16 = 25*16B, odd granules)
#define C1P 56          // conv1 smem pitch bf16 (112 B = 7*16B, odd granules)

// scratch (no allocs allowed -> __device__ globals)
__device__ float g_y0[220 * 220 * BSZ];
__device__ float g_p0s[3025 * BSZ];
__device__ float g_p0ss[3025 * BSZ];
__device__ float g_m0[BSZ], g_r0[BSZ];
__device__ float g_h1[110 * 110 * BSZ];
__device__ float g_y1[159 * 159 * BSZ];
__device__ float g_p1s[2809 * BSZ];
__device__ float g_p1ss[2809 * BSZ];
__device__ float g_m1[BSZ], g_r1[BSZ];
__device__ uint4 g_fT_hi[(size_t)BSZ * KPAD / 8];  // feat hi bf16, [b][k]
__device__ uint4 g_fT_lo[(size_t)BSZ * KPAD / 8];  // feat lo bf16, [b][k]
__device__ float g_part[SK2 * BSZ * 1000];

// ---------------------------------------------------------------------------
// conv0_mma [R14-proven]: per-location 128(b)x16(oc)x192(k) HMMA, bf16 hi/lo,
// weight loads issued first. grid (55,55), 256 threads; smem 115200 B.
// ---------------------------------------------------------------------------
__global__ void __launch_bounds__(256) conv0_mma_kernel(const float* __restrict__ x,
                                                        const float* __restrict__ w0,
                                                        const float* __restrict__ b0) {
    extern __shared__ __align__(16) char csb[];
    const uint32_t base = smem_u32(csb);
    const uint32_t PH = 0, PL = 128 * CPB, WH = 2 * 128 * CPB, WL = WH + 16 * CPB;
    const int i = blockIdx.x, j = blockIdx.y, t = threadIdx.x;

    const float2* wloc = (const float2*)(w0 + (size_t)(i * 55 + j) * 3072);
    float2 wreg[6];
#pragma unroll
    for (int p = 0; p < 6; p++) wreg[p] = __ldg(&wloc[p * 256 + t]);

    {
        const int b = t & 127, hp = t >> 7;
#pragma unroll 6
        for (int p = 0; p < 12; p++) {
            int p2 = hp * 12 + p;
            int c = p2 >> 3, di = p2 & 7;
            const float* src = x + (((size_t)(b * 3 + c) * 224) + (i * 4 + di)) * 224 + j * 4;
            float4 fa = *(const float4*)src;
            float4 fb = *(const float4*)(src + 4);
            uint32_t h0 = pack_bf16x2(fa.x, fa.y), h1 = pack_bf16x2(fa.z, fa.w);
            uint32_t h2 = pack_bf16x2(fb.x, fb.y), h3 = pack_bf16x2(fb.z, fb.w);
            uint32_t l0 = pack_bf16x2(fa.x - __uint_as_float(h0 << 16),
                                      fa.y - __uint_as_float(h0 & 0xFFFF0000u));
            uint32_t l1 = pack_bf16x2(fa.z - __uint_as_float(h1 << 16),
                                      fa.w - __uint_as_float(h1 & 0xFFFF0000u));
            uint32_t l2 = pack_bf16x2(fb.x - __uint_as_float(h2 << 16),
                                      fb.y - __uint_as_float(h2 & 0xFFFF0000u));
            uint32_t l3 = pack_bf16x2(fb.z - __uint_as_float(h3 << 16),
                                      fb.w - __uint_as_float(h3 & 0xFFFF0000u));
            uint32_t off = (uint32_t)b * CPB + (uint32_t)(c * 64 + di * 8) * 2;
            *(uint4*)(csb + PH + off) = make_uint4(h0, h1, h2, h3);
            *(uint4*)(csb + PL + off) = make_uint4(l0, l1, l2, l3);
        }
    }
#pragma unroll
    for (int p = 0; p < 6; p++) {
        int e2 = p * 256 + t;
        int oc = e2 / 96, kk = (e2 % 96) * 2;
        float2 wv = wreg[p];
        uint32_t ph = pack_bf16x2(wv.x, wv.y);
        uint32_t pl = pack_bf16x2(wv.x - __uint_as_float(ph << 16),
                                  wv.y - __uint_as_float(ph & 0xFFFF0000u));
        uint32_t off = (uint32_t)oc * CPB + (uint32_t)kk * 2;
        *(uint32_t*)(csb + WH + off) = ph;
        *(uint32_t*)(csb + WL + off) = pl;
    }
    __syncthreads();

    const int wid = t >> 5, lane = t & 31;
    const int g = lane >> 2, tg = lane & 3;
    const int tq = lane >> 3, tr = lane & 7;
    const int mbase = wid * 16;

    float acc[2][4];
#pragma unroll
    for (int nt = 0; nt < 2; nt++)
#pragma unroll
        for (int q = 0; q < 4; q++) acc[nt][q] = 0.f;

    const uint32_t raBase = (uint32_t)(mbase + (tq & 1) * 8 + tr) * CPB + (tq >> 1) * 16;
    const uint32_t rbBase = (uint32_t)((tq & 2) * 4 + tr) * CPB + (tq & 1) * 16;

#pragma unroll
    for (int kk = 0; kk < 12; kk++) {
        const uint32_t kb = kk * 32;
        uint32_t bh[4], bl[4], ah[4], al[4];
        LDSM_X4(bh, base + WH + rbBase + kb);
        LDSM_X4(bl, base + WL + rbBase + kb);
        LDSM_X4(ah, base + PH + raBase + kb);
        LDSM_X4(al, base + PL + raBase + kb);
        MMA_BF16(acc[0], ah, bh[0], bh[1]); MMA_BF16(acc[1], ah, bh[2], bh[3]);
        MMA_BF16(acc[0], ah, bl[0], bl[1]); MMA_BF16(acc[1], ah, bl[2], bl[3]);
        MMA_BF16(acc[0], al, bh[0], bh[1]); MMA_BF16(acc[1], al, bh[2], bh[3]);
    }

    int ocs[4] = {2 * tg, 2 * tg + 1, 8 + 2 * tg, 9 + 2 * tg};
    float bias[4];
#pragma unroll
    for (int q = 0; q < 4; q++) bias[q] = b0[(ocs[q] * 55 + i) * 55 + j];
    const int blk = j * 55 + i;

#pragma unroll
    for (int rh = 0; rh < 2; rh++) {
        int b = mbase + rh * 8 + g;
        float vals[4] = {acc[0][2 * rh], acc[0][2 * rh + 1],
                         acc[1][2 * rh], acc[1][2 * rh + 1]};
        float s = 0.f, ss = 0.f;
#pragma unroll
        for (int q = 0; q < 4; q++) {
            float v = fmaxf(vals[q] + bias[q], 0.f);
            int oc = ocs[q];
            g_y0[((i * 4 + (oc >> 2)) * 220 + (j * 4 + (oc & 3))) * 128 + b] = v;
            s += v;
            ss = fmaf(v, v, ss);
        }
        s  += __shfl_xor_sync(0xffffffffu, s, 1);
        s  += __shfl_xor_sync(0xffffffffu, s, 2);
        ss += __shfl_xor_sync(0xffffffffu, ss, 1);
        ss += __shfl_xor_sync(0xffffffffu, ss, 2);
        if (tg == 0) {
            g_p0s[blk * 128 + b]  = s;
            g_p0ss[blk * 128 + b] = ss;
        }
    }
}

// ---------------------------------------------------------------------------
// reduce LN partials -> mean, rstd  [R12/R14-proven monolithic form]
// ---------------------------------------------------------------------------
__global__ void ln2_kernel(int which) {
    const float* ps  = which ? g_p1s  : g_p0s;
    const float* pss = which ? g_p1ss : g_p0ss;
    float* gm        = which ? g_m1 : g_m0;
    float* gr        = which ? g_r1 : g_r0;
    const int nblk   = which ? 2809 : 3025;
    const float invn = which ? (1.f / 25281.f) : (1.f / 48400.f);
    int b = blockIdx.x, t = threadIdx.x;
    float s = 0.f, ss = 0.f;
    for (int k = t; k < nblk; k += 256) {
        s  += ps[k * 128 + b];
        ss += pss[k * 128 + b];
    }
    __shared__ float r1[8], r2[8];
    for (int o = 16; o; o >>= 1) {
        s  += __shfl_xor_sync(0xffffffffu, s, o);
        ss += __shfl_xor_sync(0xffffffffu, ss, o);
    }
    if ((t & 31) == 0) { r1[t >> 5] = s; r2[t >> 5] = ss; }
    __syncthreads();
    if (t == 0) {
        s = 0.f; ss = 0.f;
        for (int w = 0; w < 8; w++) { s += r1[w]; ss += r2[w]; }
        float m = s * invn;
        float var = ss * invn - m * m;
        gm[b] = m;
        gr[b] = rsqrtf(var + 1e-5f);
    }
}

// ---------------------------------------------------------------------------
// normalize (layer0) + 2x2 maxpool -> g_h1 [pos][b], float4 over b
// [R15-measured: 9.0us vs 9.8 scalar]
// ---------------------------------------------------------------------------
__global__ void norm_pool_kernel(const float* __restrict__ g0,
                                 const float* __restrict__ be0) {
    int idx = blockIdx.x * 256 + threadIdx.x;
    if (idx >= 32 * 110 * 110) return;
    int bq = idx & 31, pos = idx >> 5;
    int r = pos / 110, c = pos - r * 110;
    float4 m  = *(const float4*)&g_m0[bq * 4];
    float4 rs = *(const float4*)&g_r0[bq * 4];
    float4 mx = make_float4(-3.4e38f, -3.4e38f, -3.4e38f, -3.4e38f);
#pragma unroll
    for (int dr = 0; dr < 2; dr++)
#pragma unroll
        for (int dc = 0; dc < 2; dc++) {
            int P = (2 * r + dr) * 220 + 2 * c + dc;
            float4 y = *(const float4*)&g_y0[P * 128 + bq * 4];
            float gv = g0[P], bv = be0[P];
            mx.x = fmaxf(mx.x, fmaf((y.x - m.x) * rs.x, gv, bv));
            mx.y = fmaxf(mx.y, fmaf((y.y - m.y) * rs.y, gv, bv));
            mx.z = fmaxf(mx.z, fmaf((y.z - m.z) * rs.z, gv, bv));
            mx.w = fmaxf(mx.w, fmaf((y.w - m.w) * rs.w, gv, bv));
        }
    *(float4*)&g_h1[pos * 128 + bq * 4] = mx;
}

// ---------------------------------------------------------------------------
// conv1_mma [R11-proven]: per-location 128(b) x 16(oc; 9 real) x 48(k; 36
// real) HMMA, bf16 hi/lo split. grid (53,53), 128 threads (4 warps).
// ---------------------------------------------------------------------------
__global__ void __launch_bounds__(128) conv1_mma_kernel(const float* __restrict__ w1,
                                                        const float* __restrict__ b1) {
    __shared__ __align__(16) __nv_bfloat16 c1[2 * 128 * C1P + 2 * 16 * C1P];
    const uint32_t base = smem_u32(c1);
    const uint32_t PHE = 0, PLE = 128 * C1P, WHE = 2 * 128 * C1P, WLE = WHE + 16 * C1P;
    const int i = blockIdx.x, j = blockIdx.y, t = threadIdx.x;

    {
        uint32_t* wz = (uint32_t*)(c1 + WHE);
        for (int p = t; p < 896; p += 128) wz[p] = 0;
    }
    {
        uint32_t* p32 = (uint32_t*)c1;
#pragma unroll
        for (int w = 18; w < 24; w++) {
            p32[t * 28 + w] = 0;
            p32[128 * 28 + t * 28 + w] = 0;
        }
    }
    {
        uint32_t* ph32 = (uint32_t*)c1;
        uint32_t* pl32 = ph32 + 128 * 28;
#pragma unroll 6
        for (int k2 = 0; k2 < 18; k2++) {
            int k0 = 2 * k2;
            int di0 = k0 / 6, dj0 = k0 - di0 * 6;
            int di1 = (k0 + 1) / 6, dj1 = (k0 + 1) - di1 * 6;
            float v0 = g_h1[((2 * i + di0) * 110 + 2 * j + dj0) * 128 + t];
            float v1 = g_h1[((2 * i + di1) * 110 + 2 * j + dj1) * 128 + t];
            uint32_t ph = pack_bf16x2(v0, v1);
            uint32_t pl = pack_bf16x2(v0 - __uint_as_float(ph << 16),
                                      v1 - __uint_as_float(ph & 0xFFFF0000u));
            ph32[t * 28 + k2] = ph;
            pl32[t * 28 + k2] = pl;
        }
    }
    {
        const float* wloc = w1 + (i * 53 + j) * 324;
        for (int e = t; e < 324; e += 128) {
            int oc = e / 36, kk = e - oc * 36;
            float v = wloc[e];
            __nv_bfloat16 h = __float2bfloat16(v);
            __nv_bfloat16 l = __float2bfloat16(v - __bfloat162float(h));
            c1[WHE + oc * C1P + kk] = h;
            c1[WLE + oc * C1P + kk] = l;
        }
    }
    __syncthreads();

    const int wid = t >> 5, lane = t & 31;
    const int g = lane >> 2, tg = lane & 3;
    const int tq = lane >> 3, tr = lane & 7;
    const int mbase = wid * 32;

    float acc[2][2][4];
#pragma unroll
    for (int mt = 0; mt < 2; mt++)
#pragma unroll
        for (int nt = 0; nt < 2; nt++)
#pragma unroll
            for (int q = 0; q < 4; q++) acc[mt][nt][q] = 0.f;

    const uint32_t aOff = (uint32_t)((tq & 1) * 8 + tr) * 112 + (tq >> 1) * 16;
    const uint32_t bOff = (uint32_t)((tq & 2) * 4 + tr) * 112 + (tq & 1) * 16;

#pragma unroll
    for (int k16 = 0; k16 < 3; k16++) {
        const uint32_t kb = k16 * 32;
        uint32_t bh[4], bl[4];
        LDSM_X4(bh, base + WHE * 2 + bOff + kb);
        LDSM_X4(bl, base + WLE * 2 + bOff + kb);
#pragma unroll
        for (int mt = 0; mt < 2; mt++) {
            uint32_t ah[4], al[4];
            uint32_t ra = (uint32_t)(mbase + mt * 16) * 112 + aOff + kb;
            LDSM_X4(ah, base + ra);
            LDSM_X4(al, base + PLE * 2 + ra);
            MMA_BF16(acc[mt][0], ah, bh[0], bh[1]); MMA_BF16(acc[mt][1], ah, bh[2], bh[3]);
            MMA_BF16(acc[mt][0], ah, bl[0], bl[1]); MMA_BF16(acc[mt][1], ah, bl[2], bl[3]);
            MMA_BF16(acc[mt][0], al, bh[0], bh[1]); MMA_BF16(acc[mt][1], al, bh[2], bh[3]);
        }
    }

    const int loc = i * 53 + j;
    const int oc0 = 2 * tg, oc1 = 2 * tg + 1;
    const float bv0 = b1[(oc0 * 53 + i) * 53 + j];
    const float bv1 = b1[(oc1 * 53 + i) * 53 + j];
    const float bv8 = (tg == 0) ? b1[(8 * 53 + i) * 53 + j] : 0.f;

#pragma unroll
    for (int mt = 0; mt < 2; mt++)
#pragma unroll
        for (int rh = 0; rh < 2; rh++) {
            int b = mbase + mt * 16 + rh * 8 + g;
            float s = 0.f, ss = 0.f;
            float v0 = fmaxf(acc[mt][0][2 * rh] + bv0, 0.f);
            float v1 = fmaxf(acc[mt][0][2 * rh + 1] + bv1, 0.f);
            g_y1[((i * 3 + oc0 / 3) * 159 + (j * 3 + oc0 % 3)) * 128 + b] = v0;
            g_y1[((i * 3 + oc1 / 3) * 159 + (j * 3 + oc1 % 3)) * 128 + b] = v1;
            s = v0 + v1;
            ss = fmaf(v0, v0, 0.f);
            ss = fmaf(v1, v1, ss);
            if (tg == 0) {
                float v8 = fmaxf(acc[mt][1][2 * rh] + bv8, 0.f);
                g_y1[((i * 3 + 2) * 159 + (j * 3 + 2)) * 128 + b] = v8;
                s += v8;
                ss = fmaf(v8, v8, ss);
            }
            s  += __shfl_xor_sync(0xffffffffu, s, 1);
            s  += __shfl_xor_sync(0xffffffffu, s, 2);
            ss += __shfl_xor_sync(0xffffffffu, ss, 1);
            ss += __shfl_xor_sync(0xffffffffu, ss, 2);
            if (tg == 0) {
                g_p1s[loc * 128 + b]  = s;
                g_p1ss[loc * 128 + b] = ss;
            }
        }
}

// ---------------------------------------------------------------------------
// norm1t: normalize layer1 + transpose to [b][k] + bf16 hi/lo split.
// ---------------------------------------------------------------------------
__global__ void __launch_bounds__(256) norm1t_kernel(const float* __restrict__ g1,
                                                     const float* __restrict__ be1) {
    __shared__ float Tb[64][129];
    const int k0 = blockIdx.x * 64;
    const int t = threadIdx.x;
#pragma unroll
    for (int p = 0; p < 8; p++) {
        int e = p * 256 + t;
        int kl = e >> 5, bq = e & 31;
        int k = k0 + kl;
        float4 v = make_float4(0.f, 0.f, 0.f, 0.f);
        if (k < FCK) {
            float4 y = *(const float4*)&g_y1[k * 128 + bq * 4];
            float4 m = *(const float4*)&g_m1[bq * 4];
            float4 r = *(const float4*)&g_r1[bq * 4];
            float gk = g1[k], bk = be1[k];
            v.x = fmaf((y.x - m.x) * r.x, gk, bk);
            v.y = fmaf((y.y - m.y) * r.y, gk, bk);
            v.z = fmaf((y.z - m.z) * r.z, gk, bk);
            v.w = fmaf((y.w - m.w) * r.w, gk, bk);
        }
        Tb[kl][bq * 4 + 0] = v.x;
        Tb[kl][bq * 4 + 1] = v.y;
        Tb[kl][bq * 4 + 2] = v.z;
        Tb[kl][bq * 4 + 3] = v.w;
    }
    __syncthreads();

    const int b = t >> 1, half = t & 1;
    uint32_t oh[16], ol[16];
#pragma unroll
    for (int u = 0; u < 16; u++) {
        float v0 = Tb[half * 32 + 2 * u][b];
        float v1 = Tb[half * 32 + 2 * u + 1][b];
        uint32_t ph = pack_bf16x2(v0, v1);
        float h0 = __uint_as_float(ph << 16);
        float h1 = __uint_as_float(ph & 0xFFFF0000u);
        oh[u] = ph;
        ol[u] = pack_bf16x2(v0 - h0, v1 - h1);
    }
    uint32_t* dh = (uint32_t*)g_fT_hi + (size_t)b * (KPAD / 2) + (k0 + half * 32) / 2;
    uint32_t* dl = (uint32_t*)g_fT_lo + (size_t)b * (KPAD / 2) + (k0 + half * 32) / 2;
#pragma unroll
    for (int q = 0; q < 4; q++) {
        ((uint4*)dh)[q] = make_uint4(oh[4 * q], oh[4 * q + 1], oh[4 * q + 2], oh[4 * q + 3]);
        ((uint4*)dl)[q] = make_uint4(ol[4 * q], ol[4 * q + 1], ol[4 * q + 2], ol[4 * q + 3]);
    }
}

// ---------------------------------------------------------------------------
// fc_mma [R10-proven]: bf16 hi/lo-split HMMA GEMM, register-pipelined.
// grid (8, 18), 256 threads (8 warps).
// ---------------------------------------------------------------------------
__global__ void __launch_bounds__(256) fc_mma_kernel(const float* __restrict__ fcw) {
    extern __shared__ __align__(16) __nv_bfloat16 sb[];
    __nv_bfloat16* Wh = sb;                  // [128][72]
    __nv_bfloat16* Wl = Wh + 128 * FPITCH;
    __nv_bfloat16* Fh = Wl + 128 * FPITCH;
    __nv_bfloat16* Fl = Fh + 128 * FPITCH;
    const uint32_t base = smem_u32(sb);
    const uint32_t WH_OFF = 0, WL_OFF = 128 * FPITCH * 2,
                   FH_OFF = 2 * 128 * FPITCH * 2, FL_OFF = 3 * 128 * FPITCH * 2;

    const int t = threadIdx.x, wid = t >> 5, lane = t & 31;
    const int g = lane >> 2, tg = lane & 3;
    const int tq = lane >> 3, tr = lane & 7;
    const int nbase = blockIdx.x * 128;
    const int sk = blockIdx.y;

    float acc[16][4];
#pragma unroll
    for (int bt = 0; bt < 16; bt++)
#pragma unroll
        for (int q = 0; q < 4; q++) acc[bt][q] = 0.f;

    const uint32_t aRow = wid * 16 + (tq & 1) * 8 + tr;
    const uint32_t aKof = (tq >> 1) * 8;
    const uint32_t bRowB = (tq & 2) * 4 + tr;
    const uint32_t bKof = (tq & 1) * 8;

    float wv[32];
    uint4 fh[4], fl[4];
    const int wrow = t >> 6, wc0 = (t & 63);
    const int frow = t >> 3, fq = t & 7;

#define FC_LOAD_TILE(K0) do { \
    _Pragma("unroll") \
    for (int p = 0; p < 32; p++) { \
        int row = wrow + p * 4, k = (K0) + wc0; \
        int ng = nbase + row; \
        wv[p] = (ng < 1000 && k < FCK) ? __ldg(&fcw[ng * FCK + k]) : 0.f; \
    } \
    _Pragma("unroll") \
    for (int p = 0; p < 4; p++) { \
        int b = frow + p * 32; \
        size_t idx = ((size_t)b * KPAD + (K0)) / 8 + fq; \
        fh[p] = g_fT_hi[idx]; \
        fl[p] = g_fT_lo[idx]; \
    } \
} while (0)

    FC_LOAD_TILE(sk * NCHUNK * 64);

    for (int it = 0; it < NCHUNK; it++) {
        __syncthreads();
#pragma unroll
        for (int p = 0; p < 32; p++) {
            int row = wrow + p * 4, c = wc0;
            float v = wv[p];
            __nv_bfloat16 h = __float2bfloat16(v);
            __nv_bfloat16 l = __float2bfloat16(v - __bfloat162float(h));
            Wh[row * FPITCH + c] = h;
            Wl[row * FPITCH + c] = l;
        }
#pragma unroll
        for (int p = 0; p < 4; p++) {
            int b = frow + p * 32;
            *(uint4*)&Fh[b * FPITCH + fq * 8] = fh[p];
            *(uint4*)&Fl[b * FPITCH + fq * 8] = fl[p];
        }
        __syncthreads();
        if (it + 1 < NCHUNK) FC_LOAD_TILE((sk * NCHUNK + it + 1) * 64);

#pragma unroll
        for (int k16 = 0; k16 < 4; k16++) {
            uint32_t ak = (k16 * 16 + aKof) * 2;
            uint32_t ah[4], al[4];
            LDSM_X4(ah, base + WH_OFF + aRow * (FPITCH * 2) + ak);
            LDSM_X4(al, base + WL_OFF + aRow * (FPITCH * 2) + ak);
            uint32_t bk = (k16 * 16 + bKof) * 2;
#pragma unroll
            for (int bt2 = 0; bt2 < 8; bt2++) {
                uint32_t brow = bt2 * 16 + bRowB;
                uint32_t bh[4], bl[4];
                LDSM_X4(bh, base + FH_OFF + brow * (FPITCH * 2) + bk);
                LDSM_X4(bl, base + FL_OFF + brow * (FPITCH * 2) + bk);
                MMA_BF16(acc[2 * bt2],     ah, bh[0], bh[1]);
                MMA_BF16(acc[2 * bt2 + 1], ah, bh[2], bh[3]);
                MMA_BF16(acc[2 * bt2],     ah, bl[0], bl[1]);
                MMA_BF16(acc[2 * bt2 + 1], ah, bl[2], bl[3]);
                MMA_BF16(acc[2 * bt2],     al, bh[0], bh[1]);
                MMA_BF16(acc[2 * bt2 + 1], al, bh[2], bh[3]);
            }
        }
    }

    float* outp = g_part + sk * (BSZ * 1000);
    const int n0 = nbase + wid * 16 + g;
    const int n1 = n0 + 8;
#pragma unroll
    for (int bt = 0; bt < 16; bt++) {
        int b0 = bt * 8 + tg * 2;
        if (n0 < 1000) {
            outp[b0 * 1000 + n0]       = acc[bt][0];
            outp[(b0 + 1) * 1000 + n0] = acc[bt][1];
        }
        if (n1 < 1000) {
            outp[b0 * 1000 + n1]       = acc[bt][2];
            outp[(b0 + 1) * 1000 + n1] = acc[bt][3];
        }
    }
}

// ---------------------------------------------------------------------------
// reduce split-K partials (fixed order -> deterministic) + bias + softmax
// float4 over n (1000 = 4*250)
// ---------------------------------------------------------------------------
__global__ void softmax_kernel(const float* __restrict__ fcb,
                               float* __restrict__ out) {
    int b = blockIdx.x, t = threadIdx.x;
    __shared__ __align__(16) float lg[1000];
    __shared__ float red[8];
    __shared__ float bc;

    if (t < 250) {
        float4 v = *(const float4*)&fcb[4 * t];
#pragma unroll 6
        for (int s = 0; s < SK2; s++) {
            float4 pv = *(const float4*)&g_part[(s * BSZ + b) * 1000 + 4 * t];
            v.x += pv.x; v.y += pv.y; v.z += pv.z; v.w += pv.w;
        }
        *(float4*)&lg[4 * t] = v;
    }
    __syncthreads();

    float mx = -3.4e38f;
    for (int n = t; n < 1000; n += 256) mx = fmaxf(mx, lg[n]);
    for (int o = 16; o; o >>= 1) mx = fmaxf(mx, __shfl_xor_sync(0xffffffffu, mx, o));
    if ((t & 31) == 0) red[t >> 5] = mx;
    __syncthreads();
    if (t == 0) {
        float m = red[0];
        for (int w = 1; w < 8; w++) m = fmaxf(m, red[w]);
        bc = m;
    }
    __syncthreads();
    mx = bc;

    float s = 0.f;
    for (int n = t; n < 1000; n += 256) s += expf(lg[n] - mx);
    for (int o = 16; o; o >>= 1) s += __shfl_xor_sync(0xffffffffu, s, o);
    __syncthreads();
    if ((t & 31) == 0) red[t >> 5] = s;
    __syncthreads();
    if (t == 0) {
        float tot = 0.f;
        for (int w = 0; w < 8; w++) tot += red[w];
        bc = 1.f / tot;
    }
    __syncthreads();
    float inv = bc;
    for (int n = t; n < 1000; n += 256)
        out[b * 1000 + n] = expf(lg[n] - mx) * inv;
}

// ---------------------------------------------------------------------------

extern "C" void kernel_launch(void* const* d_in, const int* in_sizes, int n_in,
                              void* d_out, int out_size) {
    const float* x   = (const float*)d_in[0];
    const float* w0  = (const float*)d_in[1];
    const float* b0  = (const float*)d_in[2];
    const float* g0  = (const float*)d_in[3];
    const float* be0 = (const float*)d_in[4];
    const float* w1  = (const float*)d_in[5];
    const float* b1  = (const float*)d_in[6];
    const float* g1  = (const float*)d_in[7];
    const float* be1 = (const float*)d_in[8];
    const float* fcw = (const float*)d_in[9];
    const float* fcb = (const float*)d_in[10];
    float* out = (float*)d_out;

    const int smem0 = 2 * 128 * CPB + 2 * 16 * CPB;                   // 115200 B
    cudaFuncSetAttribute(conv0_mma_kernel, cudaFuncAttributeMaxDynamicSharedMemorySize, smem0);
    const int smemFC = 4 * 128 * FPITCH * 2;                          // 73728 B
    cudaFuncSetAttribute(fc_mma_kernel, cudaFuncAttributeMaxDynamicSharedMemorySize, smemFC);

    conv0_mma_kernel<<<dim3(55, 55), 256, smem0>>>(x, w0, b0);
    ln2_kernel<<<128, 256>>>(0);
    norm_pool_kernel<<<(32 * 110 * 110 + 255) / 256, 256>>>(g0, be0);
    conv1_mma_kernel<<<dim3(53, 53), 128>>>(w1, b1);
    ln2_kernel<<<128, 256>>>(1);
    norm1t_kernel<<<396, 256>>>(g1, be1);
    fc_mma_kernel<<<dim3(8, SK2), 256, smemFC>>>(fcw);
    softmax_kernel<<<128, 256>>>(fcb, out);
}